// round 3
// baseline (speedup 1.0000x reference)
#include <cuda_runtime.h>
#include <cstdint>

#define N_NODES 200000
#define N_GRAPHS 4000
#define C1 32
#define H 64
#define EMAX 3400000
#define NBLK ((N_NODES + 255) / 256)   // 782

// ---------------- scratch (device globals; allocation forbidden) ------------
__device__ __align__(16) float g_h1[(size_t)N_NODES * H];
__device__ __align__(16) float g_pool[(size_t)N_GRAPHS * H];
__device__ __align__(16) float g_cnt[N_GRAPHS];
__device__ int g_deg[N_NODES];       // in-degree histogram
__device__ int g_off[N_NODES];       // CSR offsets (exclusive scan of deg)
__device__ int g_cursor[N_NODES];    // scatter cursors
__device__ int g_csr[EMAX];          // src ids grouped by dst
__device__ int g_bsum[1024];         // block sums for scan
__device__ int g_boff[1024];         // block offsets
__device__ int g_idx_is_32;

// ---------------- packed f32x2 helpers (PTX-only FFMA2) ---------------------
__device__ __forceinline__ unsigned long long pack2(float a, float b) {
    unsigned long long r;
    asm("mov.b64 %0, {%1, %2};" : "=l"(r)
        : "r"(__float_as_uint(a)), "r"(__float_as_uint(b)));
    return r;
}
__device__ __forceinline__ unsigned long long bcast2(float v) {
    unsigned long long r;
    asm("mov.b64 %0, {%1, %1};" : "=l"(r) : "r"(__float_as_uint(v)));
    return r;
}
__device__ __forceinline__ void ffma2(unsigned long long& d,
                                      unsigned long long a,
                                      unsigned long long b) {
    asm("fma.rn.f32x2 %0, %1, %2, %0;" : "+l"(d) : "l"(a), "l"(b));
}

// ---------------- index dtype probe ----------------------------------------
__global__ void k_probe(const void* ei, int n_elem) {
    if (threadIdx.x == 0 && blockIdx.x == 0) {
        const long long* p = (const long long*)ei;
        int cnt = n_elem < 64 ? n_elem : 64;
        int is32 = 0;
        for (int i = 0; i < cnt; i++) {
            long long v = p[i];
            if (v < 0 || v >= N_NODES) { is32 = 1; break; }
        }
        g_idx_is_32 = is32;
    }
}
__device__ __forceinline__ int load_idx(const void* base, long long i) {
    if (g_idx_is_32) return ((const int*)base)[i];
    return (int)((const long long*)base)[i];
}

// ---------------- zero -------------------------------------------------------
__global__ void k_zero() {
    int i = blockIdx.x * blockDim.x + threadIdx.x;
    int stride = gridDim.x * blockDim.x;
    for (int j = i; j < N_NODES; j += stride) g_deg[j] = 0;
    for (int j = i; j < N_GRAPHS * H; j += stride) g_pool[j] = 0.f;
    for (int j = i; j < N_GRAPHS; j += stride) g_cnt[j] = 0.f;
}

// ---------------- CSR build --------------------------------------------------
__global__ void k_hist(const void* __restrict__ ei, int E) {
    int e = blockIdx.x * blockDim.x + threadIdx.x;
    if (e >= E) return;
    int d = load_idx(ei, (long long)e + E);
    atomicAdd(&g_deg[d], 1);
}

__global__ void k_scan1() {   // per-block sums of deg
    __shared__ int s[256];
    int i = blockIdx.x * 256 + threadIdx.x;
    s[threadIdx.x] = (i < N_NODES) ? g_deg[i] : 0;
    __syncthreads();
    for (int st = 128; st > 0; st >>= 1) {
        if (threadIdx.x < st) s[threadIdx.x] += s[threadIdx.x + st];
        __syncthreads();
    }
    if (threadIdx.x == 0) g_bsum[blockIdx.x] = s[0];
}

__global__ void k_scan2() {   // scan block sums (1 block, 1024 threads)
    __shared__ int s[1024];
    int t = threadIdx.x;
    int v = (t < NBLK) ? g_bsum[t] : 0;
    s[t] = v;
    __syncthreads();
    for (int st = 1; st < 1024; st <<= 1) {
        int add = (t >= st) ? s[t - st] : 0;
        __syncthreads();
        s[t] += add;
        __syncthreads();
    }
    if (t < NBLK) g_boff[t] = s[t] - v;   // exclusive
}

__global__ void k_scan3() {   // final offsets + cursors
    __shared__ int s[256];
    int i = blockIdx.x * 256 + threadIdx.x;
    int v = (i < N_NODES) ? g_deg[i] : 0;
    s[threadIdx.x] = v;
    __syncthreads();
    for (int st = 1; st < 256; st <<= 1) {
        int add = (threadIdx.x >= st) ? s[threadIdx.x - st] : 0;
        __syncthreads();
        s[threadIdx.x] += add;
        __syncthreads();
    }
    if (i < N_NODES) {
        int off = g_boff[blockIdx.x] + s[threadIdx.x] - v;  // exclusive
        g_off[i] = off;
        g_cursor[i] = off;
    }
}

__global__ void k_scatter(const void* __restrict__ ei, int E) {
    int e = blockIdx.x * blockDim.x + threadIdx.x;
    if (e >= E) return;
    int sidx = load_idx(ei, e);
    int d = load_idx(ei, (long long)e + E);
    int pos = atomicAdd(&g_cursor[d], 1);
    g_csr[pos] = sidx;
}

// ---------------- layer 1: gather + mean + fused SAGE GEMM -----------------
// warp per node; lane = input channel (C1 = 32)
__global__ void __launch_bounds__(256) k_layer1(const float* __restrict__ x,
                                                const float* __restrict__ Wl,
                                                const float* __restrict__ b,
                                                const float* __restrict__ Wr) {
    __shared__ __align__(16) float sWlt[C1 * H];   // [k][j] transposed
    __shared__ __align__(16) float sWrt[C1 * H];
    __shared__ float sb[H];
    __shared__ __align__(16) float sm[8][C1];
    __shared__ __align__(16) float sx[8][C1];

    for (int i = threadIdx.x; i < H * C1; i += 256) {
        int j = i / C1, k = i % C1;
        sWlt[k * H + j] = Wl[i];
        sWrt[k * H + j] = Wr[i];
    }
    for (int i = threadIdx.x; i < H; i += 256) sb[i] = b[i];
    __syncthreads();

    int warp = threadIdx.x >> 5, lane = threadIdx.x & 31;
    int n = blockIdx.x * 8 + warp;
    if (n >= N_NODES) return;

    int off = g_off[n];
    int deg = g_deg[n];
    int end = off + deg;

    float sum = 0.f;
    for (int base = off; base < end; base += 32) {
        int e = base + lane;
        int my = (e < end) ? g_csr[e] : 0;
        int cnt = min(32, end - base);
        for (int i = 0; i < cnt; i++) {
            int s = __shfl_sync(0xffffffff, my, i);
            sum += x[(size_t)s * C1 + lane];
        }
    }
    float inv = 1.f / fmaxf((float)deg, 1.f);
    sm[warp][lane] = sum * inv;
    sx[warp][lane] = x[(size_t)n * C1 + lane];
    __syncwarp();

    int j0 = lane * 2;
    unsigned long long acc = pack2(sb[j0], sb[j0 + 1]);
#pragma unroll
    for (int k = 0; k < C1; k++) {
        unsigned long long am = bcast2(sm[warp][k]);
        unsigned long long ax = bcast2(sx[warp][k]);
        unsigned long long wl = *reinterpret_cast<const unsigned long long*>(&sWlt[k * H + j0]);
        unsigned long long wr = *reinterpret_cast<const unsigned long long*>(&sWrt[k * H + j0]);
        ffma2(acc, am, wl);
        ffma2(acc, ax, wr);
    }
    float lo = fmaxf(__uint_as_float((unsigned)(acc & 0xffffffffull)), 0.f);
    float hi = fmaxf(__uint_as_float((unsigned)(acc >> 32)), 0.f);
    *reinterpret_cast<float2*>(&g_h1[(size_t)n * H + j0]) = make_float2(lo, hi);
}

// ---------------- layer 2: gather + mean + SAGE GEMM + pooled atomics ------
// warp per node; lane covers 2 of the 64 channels
__global__ void __launch_bounds__(256) k_layer2(const void* __restrict__ batch,
                                                const float* __restrict__ Wl,
                                                const float* __restrict__ b,
                                                const float* __restrict__ Wr) {
    __shared__ __align__(16) float sWlt[H * H];    // [k][j] transposed
    __shared__ __align__(16) float sWrt[H * H];
    __shared__ float sb[H];
    __shared__ __align__(16) float sm[8][H];
    __shared__ __align__(16) float sh[8][H];

    for (int i = threadIdx.x; i < H * H; i += 256) {
        int j = i / H, k = i % H;
        sWlt[k * H + j] = Wl[i];
        sWrt[k * H + j] = Wr[i];
    }
    for (int i = threadIdx.x; i < H; i += 256) sb[i] = b[i];
    __syncthreads();

    int warp = threadIdx.x >> 5, lane = threadIdx.x & 31;
    int n = blockIdx.x * 8 + warp;
    if (n >= N_NODES) return;

    int off = g_off[n];
    int deg = g_deg[n];
    int end = off + deg;

    float s0 = 0.f, s1 = 0.f;
    for (int base = off; base < end; base += 32) {
        int e = base + lane;
        int my = (e < end) ? g_csr[e] : 0;
        int cnt = min(32, end - base);
        for (int i = 0; i < cnt; i++) {
            int s = __shfl_sync(0xffffffff, my, i);
            s0 += g_h1[(size_t)s * H + lane];
            s1 += g_h1[(size_t)s * H + 32 + lane];
        }
    }
    float inv = 1.f / fmaxf((float)deg, 1.f);
    sm[warp][lane]      = s0 * inv;
    sm[warp][lane + 32] = s1 * inv;
    sh[warp][lane]      = g_h1[(size_t)n * H + lane];
    sh[warp][lane + 32] = g_h1[(size_t)n * H + 32 + lane];
    __syncwarp();

    int j0 = lane * 2;
    unsigned long long acc = pack2(sb[j0], sb[j0 + 1]);
#pragma unroll
    for (int k = 0; k < H; k++) {
        unsigned long long am = bcast2(sm[warp][k]);
        unsigned long long ah = bcast2(sh[warp][k]);
        unsigned long long wl = *reinterpret_cast<const unsigned long long*>(&sWlt[k * H + j0]);
        unsigned long long wr = *reinterpret_cast<const unsigned long long*>(&sWrt[k * H + j0]);
        ffma2(acc, am, wl);
        ffma2(acc, ah, wr);
    }
    float lo = fmaxf(__uint_as_float((unsigned)(acc & 0xffffffffull)), 0.f);
    float hi = fmaxf(__uint_as_float((unsigned)(acc >> 32)), 0.f);

    int bg = load_idx(batch, n);
    atomicAdd(reinterpret_cast<float2*>(&g_pool[(size_t)bg * H + j0]),
              make_float2(lo, hi));
    if (lane == 0) atomicAdd(&g_cnt[bg], 1.0f);
}

// ---------------- final linear ----------------------------------------------
__global__ void k_final(const float* __restrict__ Wlin,
                        const float* __restrict__ blin,
                        float* __restrict__ out) {
    int g = blockIdx.x * blockDim.x + threadIdx.x;
    if (g >= N_GRAPHS) return;
    float invc = 1.0f / fmaxf(g_cnt[g], 1.0f);
    float a0 = blin[0], a1 = blin[1];
#pragma unroll
    for (int j = 0; j < H; j++) {
        float p = g_pool[(size_t)g * H + j] * invc;
        a0 += p * Wlin[j];
        a1 += p * Wlin[H + j];
    }
    out[g * 2 + 0] = a0;
    out[g * 2 + 1] = a1;
}

// ---------------------------------------------------------------------------
extern "C" void kernel_launch(void* const* d_in, const int* in_sizes, int n_in,
                              void* d_out, int out_size) {
    const float* x     = (const float*)d_in[0];
    const void*  ei    = d_in[1];
    const void*  batch = d_in[2];
    const float* W1_l  = (const float*)d_in[3];
    const float* b1    = (const float*)d_in[4];
    const float* W1_r  = (const float*)d_in[5];
    const float* W2_l  = (const float*)d_in[6];
    const float* b2    = (const float*)d_in[7];
    const float* W2_r  = (const float*)d_in[8];
    const float* W_lin = (const float*)d_in[9];
    const float* b_lin = (const float*)d_in[10];
    float* out = (float*)d_out;

    int E = in_sizes[1] / 2;
    int eb = (E + 255) / 256;
    int nb = (N_NODES + 7) / 8;   // 25000 blocks of 8 warps

    k_probe<<<1, 32>>>(ei, in_sizes[1]);
    k_zero<<<512, 256>>>();
    k_hist<<<eb, 256>>>(ei, E);
    k_scan1<<<NBLK, 256>>>();
    k_scan2<<<1, 1024>>>();
    k_scan3<<<NBLK, 256>>>();
    k_scatter<<<eb, 256>>>(ei, E);
    k_layer1<<<nb, 256>>>(x, W1_l, b1, W1_r);
    k_layer2<<<nb, 256>>>(batch, W2_l, b2, W2_r);
    k_final<<<(N_GRAPHS + 127) / 128, 128>>>(W_lin, b_lin, out);
}

// round 4
// speedup vs baseline: 3.4902x; 3.4902x over previous
#include <cuda_runtime.h>
#include <cstdint>

#define N_NODES 200000
#define N_GRAPHS 4000
#define C1 32
#define H 64

// Scratch (device globals; allocation is forbidden)
__device__ __align__(16) float g_agg1[(size_t)N_NODES * C1];   // layer1 neighbor sums
__device__ __align__(16) float g_deg[N_NODES];                  // degrees
__device__ __align__(16) float g_h1[(size_t)N_NODES * H];       // layer1 output
__device__ __align__(16) float g_agg2[(size_t)N_NODES * H];     // layer2 neighbor sums
__device__ __align__(16) float g_pool[(size_t)N_GRAPHS * H];    // pooled sums
__device__ __align__(16) float g_cnt[N_GRAPHS];                 // nodes per graph
__device__ int g_idx_is_32;                                     // 1 if indices are int32

// ---------------------------------------------------------------------------
// Probe index dtype: if interpreting the buffer as int64 yields out-of-range
// values, the underlying data is int32.
__global__ void k_probe(const void* ei, int n_elem) {
    if (threadIdx.x == 0 && blockIdx.x == 0) {
        const long long* p = (const long long*)ei;
        int cnt = n_elem < 64 ? n_elem : 64;
        int is32 = 0;
        for (int i = 0; i < cnt; i++) {
            long long v = p[i];
            if (v < 0 || v >= N_NODES) { is32 = 1; break; }
        }
        g_idx_is_32 = is32;
    }
}
__device__ __forceinline__ int load_idx(const void* base, long long i) {
    if (g_idx_is_32) return ((const int*)base)[i];
    return (int)((const long long*)base)[i];
}

// ---------------------------------------------------------------------------
__global__ void k_zero() {
    int i = blockIdx.x * blockDim.x + threadIdx.x;
    int stride = gridDim.x * blockDim.x;
    float4 z = make_float4(0.f, 0.f, 0.f, 0.f);
    float4* a1 = reinterpret_cast<float4*>(g_agg1);
    float4* a2 = reinterpret_cast<float4*>(g_agg2);
    float4* pp = reinterpret_cast<float4*>(g_pool);
    for (int j = i; j < N_NODES * C1 / 4; j += stride) a1[j] = z;
    for (int j = i; j < N_NODES * H / 4;  j += stride) a2[j] = z;
    for (int j = i; j < N_GRAPHS * H / 4; j += stride) pp[j] = z;
    for (int j = i; j < N_NODES; j += stride) g_deg[j] = 0.f;
    for (int j = i; j < N_GRAPHS; j += stride) g_cnt[j] = 0.f;
}

// ---------------------------------------------------------------------------
// Layer-1 edge scatter: 8 float4 groups per edge (32 channels)  [known good]
__global__ void k_edge1(const float* __restrict__ x,
                        const void* __restrict__ ei, int E) {
    long long idx = (long long)blockIdx.x * blockDim.x + threadIdx.x;
    if (idx >= (long long)E * 8) return;
    long long e = idx >> 3;
    int g = (int)(idx & 7);
    int s = load_idx(ei, e);
    int d = load_idx(ei, e + E);
    float4 v = *reinterpret_cast<const float4*>(x + (size_t)s * C1 + g * 4);
    atomicAdd(reinterpret_cast<float4*>(g_agg1 + (size_t)d * C1 + g * 4), v);
    if (g == 0) atomicAdd(&g_deg[d], 1.0f);
}

// ---------------------------------------------------------------------------
// Layer-1 node update: h1 = relu(mean @ W1_l^T + b1 + x @ W1_r^T)
// float4 weight LDS, 4 output channels per iteration
__global__ void k_node1(const float* __restrict__ x,
                        const float* __restrict__ Wl,
                        const float* __restrict__ b,
                        const float* __restrict__ Wr) {
    __shared__ __align__(16) float sWl[H * C1];
    __shared__ __align__(16) float sWr[H * C1];
    __shared__ float sb[H];
    for (int i = threadIdx.x; i < H * C1; i += blockDim.x) { sWl[i] = Wl[i]; sWr[i] = Wr[i]; }
    for (int i = threadIdx.x; i < H; i += blockDim.x) sb[i] = b[i];
    __syncthreads();

    int n = blockIdx.x * blockDim.x + threadIdx.x;
    if (n >= N_NODES) return;

    float inv = 1.0f / fmaxf(g_deg[n], 1.0f);
    float m[C1], xv[C1];
    const float4* ag = reinterpret_cast<const float4*>(g_agg1 + (size_t)n * C1);
    const float4* xr = reinterpret_cast<const float4*>(x + (size_t)n * C1);
#pragma unroll
    for (int k = 0; k < C1 / 4; k++) {
        float4 a = ag[k];
        m[4 * k + 0] = a.x * inv; m[4 * k + 1] = a.y * inv;
        m[4 * k + 2] = a.z * inv; m[4 * k + 3] = a.w * inv;
        float4 xb = xr[k];
        xv[4 * k + 0] = xb.x; xv[4 * k + 1] = xb.y;
        xv[4 * k + 2] = xb.z; xv[4 * k + 3] = xb.w;
    }
#pragma unroll
    for (int j = 0; j < H; j += 4) {
        float acc[4];
#pragma unroll
        for (int t = 0; t < 4; t++) acc[t] = sb[j + t];
#pragma unroll
        for (int k4 = 0; k4 < C1 / 4; k4++) {
#pragma unroll
            for (int t = 0; t < 4; t++) {
                float4 wl = *reinterpret_cast<const float4*>(&sWl[(j + t) * C1 + k4 * 4]);
                float4 wr = *reinterpret_cast<const float4*>(&sWr[(j + t) * C1 + k4 * 4]);
                acc[t] += m[4 * k4 + 0] * wl.x + m[4 * k4 + 1] * wl.y
                        + m[4 * k4 + 2] * wl.z + m[4 * k4 + 3] * wl.w
                        + xv[4 * k4 + 0] * wr.x + xv[4 * k4 + 1] * wr.y
                        + xv[4 * k4 + 2] * wr.z + xv[4 * k4 + 3] * wr.w;
            }
        }
        float4 o;
        o.x = fmaxf(acc[0], 0.f); o.y = fmaxf(acc[1], 0.f);
        o.z = fmaxf(acc[2], 0.f); o.w = fmaxf(acc[3], 0.f);
        *reinterpret_cast<float4*>(&g_h1[(size_t)n * H + j]) = o;
    }
}

// ---------------------------------------------------------------------------
// Layer-2 edge scatter: 16 float4 groups per edge (64 channels)  [known good]
__global__ void k_edge2(const void* __restrict__ ei, int E) {
    long long idx = (long long)blockIdx.x * blockDim.x + threadIdx.x;
    if (idx >= (long long)E * 16) return;
    long long e = idx >> 4;
    int g = (int)(idx & 15);
    int s = load_idx(ei, e);
    int d = load_idx(ei, e + E);
    float4 v = *reinterpret_cast<const float4*>(g_h1 + (size_t)s * H + g * 4);
    atomicAdd(reinterpret_cast<float4*>(g_agg2 + (size_t)d * H + g * 4), v);
}

// ---------------------------------------------------------------------------
// Layer-2 node update + fused pooling: pool[batch[n]] += relu(SAGE2(n))
__global__ void __launch_bounds__(128) k_node2(const void* __restrict__ batch,
                                               const float* __restrict__ Wl,
                                               const float* __restrict__ b,
                                               const float* __restrict__ Wr) {
    __shared__ __align__(16) float sWl[H * H];
    __shared__ __align__(16) float sWr[H * H];
    __shared__ float sb[H];
    for (int i = threadIdx.x; i < H * H; i += blockDim.x) { sWl[i] = Wl[i]; sWr[i] = Wr[i]; }
    for (int i = threadIdx.x; i < H; i += blockDim.x) sb[i] = b[i];
    __syncthreads();

    int n = blockIdx.x * blockDim.x + threadIdx.x;
    if (n >= N_NODES) return;

    float inv = 1.0f / fmaxf(g_deg[n], 1.0f);
    float m[H], hv[H];
    const float4* ag = reinterpret_cast<const float4*>(g_agg2 + (size_t)n * H);
    const float4* hr = reinterpret_cast<const float4*>(g_h1 + (size_t)n * H);
#pragma unroll
    for (int k = 0; k < H / 4; k++) {
        float4 a = ag[k];
        m[4 * k + 0] = a.x * inv; m[4 * k + 1] = a.y * inv;
        m[4 * k + 2] = a.z * inv; m[4 * k + 3] = a.w * inv;
        float4 hb = hr[k];
        hv[4 * k + 0] = hb.x; hv[4 * k + 1] = hb.y;
        hv[4 * k + 2] = hb.z; hv[4 * k + 3] = hb.w;
    }

    int bg = load_idx(batch, n);
    float* poolrow = g_pool + (size_t)bg * H;

#pragma unroll
    for (int j = 0; j < H; j += 4) {
        float acc[4];
#pragma unroll
        for (int t = 0; t < 4; t++) acc[t] = sb[j + t];
#pragma unroll
        for (int k4 = 0; k4 < H / 4; k4++) {
#pragma unroll
            for (int t = 0; t < 4; t++) {
                float4 wl = *reinterpret_cast<const float4*>(&sWl[(j + t) * H + k4 * 4]);
                float4 wr = *reinterpret_cast<const float4*>(&sWr[(j + t) * H + k4 * 4]);
                acc[t] += m[4 * k4 + 0] * wl.x + m[4 * k4 + 1] * wl.y
                        + m[4 * k4 + 2] * wl.z + m[4 * k4 + 3] * wl.w
                        + hv[4 * k4 + 0] * wr.x + hv[4 * k4 + 1] * wr.y
                        + hv[4 * k4 + 2] * wr.z + hv[4 * k4 + 3] * wr.w;
            }
        }
        float4 o;
        o.x = fmaxf(acc[0], 0.f); o.y = fmaxf(acc[1], 0.f);
        o.z = fmaxf(acc[2], 0.f); o.w = fmaxf(acc[3], 0.f);
        atomicAdd(reinterpret_cast<float4*>(poolrow + j), o);
    }
    atomicAdd(&g_cnt[bg], 1.0f);
}

// ---------------------------------------------------------------------------
// Final linear: out[G,2]
__global__ void k_final(const float* __restrict__ Wlin,
                        const float* __restrict__ blin,
                        float* __restrict__ out) {
    int g = blockIdx.x * blockDim.x + threadIdx.x;
    if (g >= N_GRAPHS) return;
    float invc = 1.0f / fmaxf(g_cnt[g], 1.0f);
    float a0 = blin[0], a1 = blin[1];
#pragma unroll
    for (int j = 0; j < H; j++) {
        float p = g_pool[(size_t)g * H + j] * invc;
        a0 += p * Wlin[j];
        a1 += p * Wlin[H + j];
    }
    out[g * 2 + 0] = a0;
    out[g * 2 + 1] = a1;
}

// ---------------------------------------------------------------------------
extern "C" void kernel_launch(void* const* d_in, const int* in_sizes, int n_in,
                              void* d_out, int out_size) {
    const float* x     = (const float*)d_in[0];
    const void*  ei    = d_in[1];
    const void*  batch = d_in[2];
    const float* W1_l  = (const float*)d_in[3];
    const float* b1    = (const float*)d_in[4];
    const float* W1_r  = (const float*)d_in[5];
    const float* W2_l  = (const float*)d_in[6];
    const float* b2    = (const float*)d_in[7];
    const float* W2_r  = (const float*)d_in[8];
    const float* W_lin = (const float*)d_in[9];
    const float* b_lin = (const float*)d_in[10];
    float* out = (float*)d_out;

    int E = in_sizes[1] / 2;

    k_probe<<<1, 32>>>(ei, in_sizes[1]);
    k_zero<<<1024, 256>>>();
    {
        long long t = (long long)E * 8;
        k_edge1<<<(unsigned)((t + 255) / 256), 256>>>(x, ei, E);
    }
    k_node1<<<(N_NODES + 255) / 256, 256>>>(x, W1_l, b1, W1_r);
    {
        long long t = (long long)E * 16;
        k_edge2<<<(unsigned)((t + 255) / 256), 256>>>(ei, E);
    }
    k_node2<<<(N_NODES + 127) / 128, 128>>>(batch, W2_l, b2, W2_r);
    k_final<<<(N_GRAPHS + 127) / 128, 128>>>(W_lin, b_lin, out);
}

// round 7
// speedup vs baseline: 4.3317x; 1.2411x over previous
#include <cuda_runtime.h>
#include <cstdint>

#define N_NODES 200000
#define N_GRAPHS 4000
#define C1 32
#define H 64
#define EMAX 3400000
#define NBLK ((N_NODES + 255) / 256)   // 782

// ---------------- scratch (device globals; allocation forbidden) ------------
__device__ __align__(16) float g_agg1[(size_t)N_NODES * C1];   // layer1 neighbor sums
__device__ __align__(16) float g_deg[N_NODES];                  // degrees (float)
__device__ __align__(16) float g_h1[(size_t)N_NODES * H];       // layer1 output
__device__ __align__(16) float g_agg2[(size_t)N_NODES * H];     // layer2 neighbor sums
__device__ __align__(16) float g_pool[(size_t)N_GRAPHS * H];    // pooled sums
__device__ __align__(16) float g_cnt[N_GRAPHS];                 // nodes per graph
__device__ int g_degi[N_NODES];     // in-degree histogram (int)
__device__ int g_off[N_NODES];      // CSR offsets
__device__ int g_cursor[N_NODES];   // scatter cursors
__device__ int g_csr[EMAX];         // src ids grouped by dst
__device__ int g_bsum[1024];
__device__ int g_boff[1024];
__device__ int g_idx_is_32;

// ---------------- index dtype probe ----------------------------------------
__global__ void k_probe(const void* ei, int n_elem) {
    if (threadIdx.x == 0 && blockIdx.x == 0) {
        const long long* p = (const long long*)ei;
        int cnt = n_elem < 64 ? n_elem : 64;
        int is32 = 0;
        for (int i = 0; i < cnt; i++) {
            long long v = p[i];
            if (v < 0 || v >= N_NODES) { is32 = 1; break; }
        }
        g_idx_is_32 = is32;
    }
}
__device__ __forceinline__ int load_idx(const void* base, long long i) {
    if (g_idx_is_32) return ((const int*)base)[i];
    return (int)((const long long*)base)[i];
}

// ---------------- zero (pool + counters only) -------------------------------
__global__ void k_zero() {
    int i = blockIdx.x * blockDim.x + threadIdx.x;
    int stride = gridDim.x * blockDim.x;
    for (int j = i; j < N_GRAPHS * H; j += stride) g_pool[j] = 0.f;
    for (int j = i; j < N_GRAPHS; j += stride) g_cnt[j] = 0.f;
    for (int j = i; j < N_NODES; j += stride) g_degi[j] = 0;
}

// ---------------- CSR build --------------------------------------------------
__global__ void k_hist(const void* __restrict__ ei, int E) {
    int e = blockIdx.x * blockDim.x + threadIdx.x;
    if (e >= E) return;
    int d = load_idx(ei, (long long)e + E);
    atomicAdd(&g_degi[d], 1);
}

__global__ void k_scan1() {   // per-block sums of degi
    __shared__ int s[256];
    int i = blockIdx.x * 256 + threadIdx.x;
    s[threadIdx.x] = (i < N_NODES) ? g_degi[i] : 0;
    __syncthreads();
    for (int st = 128; st > 0; st >>= 1) {
        if (threadIdx.x < st) s[threadIdx.x] += s[threadIdx.x + st];
        __syncthreads();
    }
    if (threadIdx.x == 0) g_bsum[blockIdx.x] = s[0];
}

__global__ void k_scan2() {   // scan block sums (1 block, 1024 threads)
    __shared__ int s[1024];
    int t = threadIdx.x;
    int v = (t < NBLK) ? g_bsum[t] : 0;
    s[t] = v;
    __syncthreads();
    for (int st = 1; st < 1024; st <<= 1) {
        int add = (t >= st) ? s[t - st] : 0;
        __syncthreads();
        s[t] += add;
        __syncthreads();
    }
    if (t < NBLK) g_boff[t] = s[t] - v;   // exclusive
}

__global__ void k_scan3() {   // final offsets + cursors
    __shared__ int s[256];
    int i = blockIdx.x * 256 + threadIdx.x;
    int v = (i < N_NODES) ? g_degi[i] : 0;
    s[threadIdx.x] = v;
    __syncthreads();
    for (int st = 1; st < 256; st <<= 1) {
        int add = (threadIdx.x >= st) ? s[threadIdx.x - st] : 0;
        __syncthreads();
        s[threadIdx.x] += add;
        __syncthreads();
    }
    if (i < N_NODES) {
        int off = g_boff[blockIdx.x] + s[threadIdx.x] - v;  // exclusive
        g_off[i] = off;
        g_cursor[i] = off;
    }
}

__global__ void k_scatter(const void* __restrict__ ei, int E) {
    int e = blockIdx.x * blockDim.x + threadIdx.x;
    if (e >= E) return;
    int sidx = load_idx(ei, e);
    int d = load_idx(ei, (long long)e + E);
    int pos = atomicAdd(&g_cursor[d], 1);
    g_csr[pos] = sidx;
}

// ---------------- layer-1 gather: warp per node, lane-parallel --------------
// lane = sub*8 + g : sub in [0,4) handles interleaved edges, g = float4 group
__global__ void __launch_bounds__(256) k_gather1(const float* __restrict__ x) {
    int warp = threadIdx.x >> 5, lane = threadIdx.x & 31;
    int n = blockIdx.x * 8 + warp;
    if (n >= N_NODES) return;
    int off = g_off[n];
    int deg = g_degi[n];
    int end = off + deg;
    int sub = lane >> 3, g = lane & 7;

    float4 acc = make_float4(0.f, 0.f, 0.f, 0.f);
    for (int e = off + sub; e < end; e += 4) {
        int s = g_csr[e];
        float4 v = *reinterpret_cast<const float4*>(x + (size_t)s * C1 + g * 4);
        acc.x += v.x; acc.y += v.y; acc.z += v.z; acc.w += v.w;
    }
#pragma unroll
    for (int d = 16; d >= 8; d >>= 1) {
        acc.x += __shfl_xor_sync(0xffffffff, acc.x, d);
        acc.y += __shfl_xor_sync(0xffffffff, acc.y, d);
        acc.z += __shfl_xor_sync(0xffffffff, acc.z, d);
        acc.w += __shfl_xor_sync(0xffffffff, acc.w, d);
    }
    if (lane < 8)
        *reinterpret_cast<float4*>(g_agg1 + (size_t)n * C1 + g * 4) = acc;
    if (lane == 0) g_deg[n] = (float)deg;
}

// ---------------- layer-1 node update (unchanged, measured 95us) ------------
__global__ void k_node1(const float* __restrict__ x,
                        const float* __restrict__ Wl,
                        const float* __restrict__ b,
                        const float* __restrict__ Wr) {
    __shared__ __align__(16) float sWl[H * C1];
    __shared__ __align__(16) float sWr[H * C1];
    __shared__ float sb[H];
    for (int i = threadIdx.x; i < H * C1; i += blockDim.x) { sWl[i] = Wl[i]; sWr[i] = Wr[i]; }
    for (int i = threadIdx.x; i < H; i += blockDim.x) sb[i] = b[i];
    __syncthreads();

    int n = blockIdx.x * blockDim.x + threadIdx.x;
    if (n >= N_NODES) return;

    float inv = 1.0f / fmaxf(g_deg[n], 1.0f);
    float m[C1], xv[C1];
    const float4* ag = reinterpret_cast<const float4*>(g_agg1 + (size_t)n * C1);
    const float4* xr = reinterpret_cast<const float4*>(x + (size_t)n * C1);
#pragma unroll
    for (int k = 0; k < C1 / 4; k++) {
        float4 a = ag[k];
        m[4 * k + 0] = a.x * inv; m[4 * k + 1] = a.y * inv;
        m[4 * k + 2] = a.z * inv; m[4 * k + 3] = a.w * inv;
        float4 xb = xr[k];
        xv[4 * k + 0] = xb.x; xv[4 * k + 1] = xb.y;
        xv[4 * k + 2] = xb.z; xv[4 * k + 3] = xb.w;
    }
#pragma unroll
    for (int j = 0; j < H; j += 4) {
        float acc[4];
#pragma unroll
        for (int t = 0; t < 4; t++) acc[t] = sb[j + t];
#pragma unroll
        for (int k4 = 0; k4 < C1 / 4; k4++) {
#pragma unroll
            for (int t = 0; t < 4; t++) {
                float4 wl = *reinterpret_cast<const float4*>(&sWl[(j + t) * C1 + k4 * 4]);
                float4 wr = *reinterpret_cast<const float4*>(&sWr[(j + t) * C1 + k4 * 4]);
                acc[t] += m[4 * k4 + 0] * wl.x + m[4 * k4 + 1] * wl.y
                        + m[4 * k4 + 2] * wl.z + m[4 * k4 + 3] * wl.w
                        + xv[4 * k4 + 0] * wr.x + xv[4 * k4 + 1] * wr.y
                        + xv[4 * k4 + 2] * wr.z + xv[4 * k4 + 3] * wr.w;
            }
        }
        float4 o;
        o.x = fmaxf(acc[0], 0.f); o.y = fmaxf(acc[1], 0.f);
        o.z = fmaxf(acc[2], 0.f); o.w = fmaxf(acc[3], 0.f);
        *reinterpret_cast<float4*>(&g_h1[(size_t)n * H + j]) = o;
    }
}

// ---------------- layer-2 gather: warp per node, lane-parallel --------------
// lane = sub*16 + g : sub in [0,2) interleaved edges, g = float4 group of 16
__global__ void __launch_bounds__(256) k_gather2() {
    int warp = threadIdx.x >> 5, lane = threadIdx.x & 31;
    int n = blockIdx.x * 8 + warp;
    if (n >= N_NODES) return;
    int off = g_off[n];
    int deg = g_degi[n];
    int end = off + deg;
    int sub = lane >> 4, g = lane & 15;

    float4 acc = make_float4(0.f, 0.f, 0.f, 0.f);
    for (int e = off + sub; e < end; e += 2) {
        int s = g_csr[e];
        float4 v = *reinterpret_cast<const float4*>(g_h1 + (size_t)s * H + g * 4);
        acc.x += v.x; acc.y += v.y; acc.z += v.z; acc.w += v.w;
    }
    acc.x += __shfl_xor_sync(0xffffffff, acc.x, 16);
    acc.y += __shfl_xor_sync(0xffffffff, acc.y, 16);
    acc.z += __shfl_xor_sync(0xffffffff, acc.z, 16);
    acc.w += __shfl_xor_sync(0xffffffff, acc.w, 16);
    if (lane < 16)
        *reinterpret_cast<float4*>(g_agg2 + (size_t)n * H + g * 4) = acc;
}

// ---------------- layer-2 node update + fused pooling (unchanged) -----------
__global__ void __launch_bounds__(128) k_node2(const void* __restrict__ batch,
                                               const float* __restrict__ Wl,
                                               const float* __restrict__ b,
                                               const float* __restrict__ Wr) {
    __shared__ __align__(16) float sWl[H * H];
    __shared__ __align__(16) float sWr[H * H];
    __shared__ float sb[H];
    for (int i = threadIdx.x; i < H * H; i += blockDim.x) { sWl[i] = Wl[i]; sWr[i] = Wr[i]; }
    for (int i = threadIdx.x; i < H; i += blockDim.x) sb[i] = b[i];
    __syncthreads();

    int n = blockIdx.x * blockDim.x + threadIdx.x;
    if (n >= N_NODES) return;

    float inv = 1.0f / fmaxf(g_deg[n], 1.0f);
    float m[H], hv[H];
    const float4* ag = reinterpret_cast<const float4*>(g_agg2 + (size_t)n * H);
    const float4* hr = reinterpret_cast<const float4*>(g_h1 + (size_t)n * H);
#pragma unroll
    for (int k = 0; k < H / 4; k++) {
        float4 a = ag[k];
        m[4 * k + 0] = a.x * inv; m[4 * k + 1] = a.y * inv;
        m[4 * k + 2] = a.z * inv; m[4 * k + 3] = a.w * inv;
        float4 hb = hr[k];
        hv[4 * k + 0] = hb.x; hv[4 * k + 1] = hb.y;
        hv[4 * k + 2] = hb.z; hv[4 * k + 3] = hb.w;
    }

    int bg = load_idx(batch, n);
    float* poolrow = g_pool + (size_t)bg * H;

#pragma unroll
    for (int j = 0; j < H; j += 4) {
        float acc[4];
#pragma unroll
        for (int t = 0; t < 4; t++) acc[t] = sb[j + t];
#pragma unroll
        for (int k4 = 0; k4 < H / 4; k4++) {
#pragma unroll
            for (int t = 0; t < 4; t++) {
                float4 wl = *reinterpret_cast<const float4*>(&sWl[(j + t) * H + k4 * 4]);
                float4 wr = *reinterpret_cast<const float4*>(&sWr[(j + t) * H + k4 * 4]);
                acc[t] += m[4 * k4 + 0] * wl.x + m[4 * k4 + 1] * wl.y
                        + m[4 * k4 + 2] * wl.z + m[4 * k4 + 3] * wl.w
                        + hv[4 * k4 + 0] * wr.x + hv[4 * k4 + 1] * wr.y
                        + hv[4 * k4 + 2] * wr.z + hv[4 * k4 + 3] * wr.w;
            }
        }
        float4 o;
        o.x = fmaxf(acc[0], 0.f); o.y = fmaxf(acc[1], 0.f);
        o.z = fmaxf(acc[2], 0.f); o.w = fmaxf(acc[3], 0.f);
        atomicAdd(reinterpret_cast<float4*>(poolrow + j), o);
    }
    atomicAdd(&g_cnt[bg], 1.0f);
}

// ---------------- final linear ----------------------------------------------
__global__ void k_final(const float* __restrict__ Wlin,
                        const float* __restrict__ blin,
                        float* __restrict__ out) {
    int g = blockIdx.x * blockDim.x + threadIdx.x;
    if (g >= N_GRAPHS) return;
    float invc = 1.0f / fmaxf(g_cnt[g], 1.0f);
    float a0 = blin[0], a1 = blin[1];
#pragma unroll
    for (int j = 0; j < H; j++) {
        float p = g_pool[(size_t)g * H + j] * invc;
        a0 += p * Wlin[j];
        a1 += p * Wlin[H + j];
    }
    out[g * 2 + 0] = a0;
    out[g * 2 + 1] = a1;
}

// ---------------------------------------------------------------------------
extern "C" void kernel_launch(void* const* d_in, const int* in_sizes, int n_in,
                              void* d_out, int out_size) {
    const float* x     = (const float*)d_in[0];
    const void*  ei    = d_in[1];
    const void*  batch = d_in[2];
    const float* W1_l  = (const float*)d_in[3];
    const float* b1    = (const float*)d_in[4];
    const float* W1_r  = (const float*)d_in[5];
    const float* W2_l  = (const float*)d_in[6];
    const float* b2    = (const float*)d_in[7];
    const float* W2_r  = (const float*)d_in[8];
    const float* W_lin = (const float*)d_in[9];
    const float* b_lin = (const float*)d_in[10];
    float* out = (float*)d_out;

    int E = in_sizes[1] / 2;
    int eb = (E + 255) / 256;
    int nb8 = (N_NODES + 7) / 8;   // 25000 blocks of 8 warps

    k_probe<<<1, 32>>>(ei, in_sizes[1]);
    k_zero<<<256, 256>>>();
    k_hist<<<eb, 256>>>(ei, E);
    k_scan1<<<NBLK, 256>>>();
    k_scan2<<<1, 1024>>>();
    k_scan3<<<NBLK, 256>>>();
    k_scatter<<<eb, 256>>>(ei, E);
    k_gather1<<<nb8, 256>>>(x);
    k_node1<<<(N_NODES + 255) / 256, 256>>>(x, W1_l, b1, W1_r);
    k_gather2<<<nb8, 256>>>();
    k_node2<<<(N_NODES + 127) / 128, 128>>>(batch, W2_l, b2, W2_r);
    k_final<<<(N_GRAPHS + 127) / 128, 128>>>(W_lin, b_lin, out);
}

// round 8
// speedup vs baseline: 5.0978x; 1.1769x over previous
#include <cuda_runtime.h>
#include <cstdint>

#define N_NODES 200000
#define N_GRAPHS 4000
#define C1 32
#define H 64
#define EMAX 3400000
#define NBLK ((N_NODES + 255) / 256)   // 782

// ---------------- scratch (device globals; allocation forbidden) ------------
__device__ __align__(16) float g_agg1[(size_t)N_NODES * C1];   // layer1 neighbor MEAN
__device__ __align__(16) float g_h1[(size_t)N_NODES * H];       // layer1 output
__device__ __align__(16) float g_agg2[(size_t)N_NODES * H];     // layer2 neighbor MEAN
__device__ __align__(16) float g_pool[(size_t)N_GRAPHS * H];    // pooled sums
__device__ __align__(16) float g_cnt[N_GRAPHS];                 // nodes per graph
__device__ int g_degi[N_NODES];     // in-degree histogram (int)
__device__ int g_off[N_NODES];      // CSR offsets
__device__ int g_cursor[N_NODES];   // scatter cursors
__device__ int g_csr[EMAX];         // src ids grouped by dst
__device__ int g_bsum[1024];
__device__ int g_boff[1024];
__device__ int g_idx_is_32;

__device__ __forceinline__ int load_idx(const void* base, long long i) {
    if (g_idx_is_32) return ((const int*)base)[i];
    return (int)((const long long*)base)[i];
}

// ---------------- zero + index-dtype probe ----------------------------------
__global__ void k_zero(const void* ei, int n_elem) {
    int i = blockIdx.x * blockDim.x + threadIdx.x;
    int stride = gridDim.x * blockDim.x;
    if (blockIdx.x == 0 && threadIdx.x == 0) {
        const long long* p = (const long long*)ei;
        int cnt = n_elem < 64 ? n_elem : 64;
        int is32 = 0;
        for (int k = 0; k < cnt; k++) {
            long long v = p[k];
            if (v < 0 || v >= N_NODES) { is32 = 1; break; }
        }
        g_idx_is_32 = is32;
    }
    for (int j = i; j < N_GRAPHS * H; j += stride) g_pool[j] = 0.f;
    for (int j = i; j < N_GRAPHS; j += stride) g_cnt[j] = 0.f;
    for (int j = i; j < N_NODES; j += stride) g_degi[j] = 0;
}

// ---------------- CSR build --------------------------------------------------
__global__ void k_hist(const void* __restrict__ ei, int E) {
    int e = blockIdx.x * blockDim.x + threadIdx.x;
    if (e >= E) return;
    int d = load_idx(ei, (long long)e + E);
    atomicAdd(&g_degi[d], 1);
}

__global__ void k_scan1() {
    __shared__ int s[256];
    int i = blockIdx.x * 256 + threadIdx.x;
    s[threadIdx.x] = (i < N_NODES) ? g_degi[i] : 0;
    __syncthreads();
    for (int st = 128; st > 0; st >>= 1) {
        if (threadIdx.x < st) s[threadIdx.x] += s[threadIdx.x + st];
        __syncthreads();
    }
    if (threadIdx.x == 0) g_bsum[blockIdx.x] = s[0];
}

__global__ void k_scan2() {
    __shared__ int s[1024];
    int t = threadIdx.x;
    int v = (t < NBLK) ? g_bsum[t] : 0;
    s[t] = v;
    __syncthreads();
    for (int st = 1; st < 1024; st <<= 1) {
        int add = (t >= st) ? s[t - st] : 0;
        __syncthreads();
        s[t] += add;
        __syncthreads();
    }
    if (t < NBLK) g_boff[t] = s[t] - v;   // exclusive
}

__global__ void k_scan3() {
    __shared__ int s[256];
    int i = blockIdx.x * 256 + threadIdx.x;
    int v = (i < N_NODES) ? g_degi[i] : 0;
    s[threadIdx.x] = v;
    __syncthreads();
    for (int st = 1; st < 256; st <<= 1) {
        int add = (threadIdx.x >= st) ? s[threadIdx.x - st] : 0;
        __syncthreads();
        s[threadIdx.x] += add;
        __syncthreads();
    }
    if (i < N_NODES) {
        int off = g_boff[blockIdx.x] + s[threadIdx.x] - v;
        g_off[i] = off;
        g_cursor[i] = off;
    }
}

__global__ void k_scatter(const void* __restrict__ ei, int E) {
    int e = blockIdx.x * blockDim.x + threadIdx.x;
    if (e >= E) return;
    int sidx = load_idx(ei, e);
    int d = load_idx(ei, (long long)e + E);
    int pos = atomicAdd(&g_cursor[d], 1);
    g_csr[pos] = sidx;
}

// ---------------- layer-1 gather (stores MEAN), 2x unrolled -----------------
// lane = sub*8 + g : sub in [0,4) interleaved edges, g = float4 group
__global__ void __launch_bounds__(256) k_gather1(const float* __restrict__ x) {
    int warp = threadIdx.x >> 5, lane = threadIdx.x & 31;
    int n = blockIdx.x * 8 + warp;
    if (n >= N_NODES) return;
    int off = g_off[n];
    int deg = g_degi[n];
    int end = off + deg;
    int sub = lane >> 3, g = lane & 7;

    float4 acc = make_float4(0.f, 0.f, 0.f, 0.f);
    int e = off + sub;
    for (; e + 4 < end; e += 8) {
        int s0 = g_csr[e];
        int s1 = g_csr[e + 4];
        float4 v0 = *reinterpret_cast<const float4*>(x + (size_t)s0 * C1 + g * 4);
        float4 v1 = *reinterpret_cast<const float4*>(x + (size_t)s1 * C1 + g * 4);
        acc.x += v0.x + v1.x; acc.y += v0.y + v1.y;
        acc.z += v0.z + v1.z; acc.w += v0.w + v1.w;
    }
    if (e < end) {
        int s = g_csr[e];
        float4 v = *reinterpret_cast<const float4*>(x + (size_t)s * C1 + g * 4);
        acc.x += v.x; acc.y += v.y; acc.z += v.z; acc.w += v.w;
    }
#pragma unroll
    for (int d = 16; d >= 8; d >>= 1) {
        acc.x += __shfl_xor_sync(0xffffffff, acc.x, d);
        acc.y += __shfl_xor_sync(0xffffffff, acc.y, d);
        acc.z += __shfl_xor_sync(0xffffffff, acc.z, d);
        acc.w += __shfl_xor_sync(0xffffffff, acc.w, d);
    }
    if (lane < 8) {
        float inv = 1.f / fmaxf((float)deg, 1.f);
        acc.x *= inv; acc.y *= inv; acc.z *= inv; acc.w *= inv;
        *reinterpret_cast<float4*>(g_agg1 + (size_t)n * C1 + g * 4) = acc;
    }
}

// ---------------- layer-1 node update (unchanged structure; agg1 is mean) ---
__global__ void k_node1(const float* __restrict__ x,
                        const float* __restrict__ Wl,
                        const float* __restrict__ b,
                        const float* __restrict__ Wr) {
    __shared__ __align__(16) float sWl[H * C1];
    __shared__ __align__(16) float sWr[H * C1];
    __shared__ float sb[H];
    for (int i = threadIdx.x; i < H * C1; i += blockDim.x) { sWl[i] = Wl[i]; sWr[i] = Wr[i]; }
    for (int i = threadIdx.x; i < H; i += blockDim.x) sb[i] = b[i];
    __syncthreads();

    int n = blockIdx.x * blockDim.x + threadIdx.x;
    if (n >= N_NODES) return;

    float m[C1], xv[C1];
    const float4* ag = reinterpret_cast<const float4*>(g_agg1 + (size_t)n * C1);
    const float4* xr = reinterpret_cast<const float4*>(x + (size_t)n * C1);
#pragma unroll
    for (int k = 0; k < C1 / 4; k++) {
        float4 a = ag[k];
        m[4 * k + 0] = a.x; m[4 * k + 1] = a.y;
        m[4 * k + 2] = a.z; m[4 * k + 3] = a.w;
        float4 xb = xr[k];
        xv[4 * k + 0] = xb.x; xv[4 * k + 1] = xb.y;
        xv[4 * k + 2] = xb.z; xv[4 * k + 3] = xb.w;
    }
#pragma unroll
    for (int j = 0; j < H; j += 4) {
        float acc[4];
#pragma unroll
        for (int t = 0; t < 4; t++) acc[t] = sb[j + t];
#pragma unroll
        for (int k4 = 0; k4 < C1 / 4; k4++) {
#pragma unroll
            for (int t = 0; t < 4; t++) {
                float4 wl = *reinterpret_cast<const float4*>(&sWl[(j + t) * C1 + k4 * 4]);
                float4 wr = *reinterpret_cast<const float4*>(&sWr[(j + t) * C1 + k4 * 4]);
                acc[t] += m[4 * k4 + 0] * wl.x + m[4 * k4 + 1] * wl.y
                        + m[4 * k4 + 2] * wl.z + m[4 * k4 + 3] * wl.w
                        + xv[4 * k4 + 0] * wr.x + xv[4 * k4 + 1] * wr.y
                        + xv[4 * k4 + 2] * wr.z + xv[4 * k4 + 3] * wr.w;
            }
        }
        float4 o;
        o.x = fmaxf(acc[0], 0.f); o.y = fmaxf(acc[1], 0.f);
        o.z = fmaxf(acc[2], 0.f); o.w = fmaxf(acc[3], 0.f);
        *reinterpret_cast<float4*>(&g_h1[(size_t)n * H + j]) = o;
    }
}

// ---------------- layer-2 gather (stores MEAN), 2x unrolled -----------------
// lane = sub*16 + g : sub in [0,2), g = float4 group of 16
__global__ void __launch_bounds__(256) k_gather2() {
    int warp = threadIdx.x >> 5, lane = threadIdx.x & 31;
    int n = blockIdx.x * 8 + warp;
    if (n >= N_NODES) return;
    int off = g_off[n];
    int deg = g_degi[n];
    int end = off + deg;
    int sub = lane >> 4, g = lane & 15;

    float4 acc = make_float4(0.f, 0.f, 0.f, 0.f);
    int e = off + sub;
    for (; e + 2 < end; e += 4) {
        int s0 = g_csr[e];
        int s1 = g_csr[e + 2];
        float4 v0 = *reinterpret_cast<const float4*>(g_h1 + (size_t)s0 * H + g * 4);
        float4 v1 = *reinterpret_cast<const float4*>(g_h1 + (size_t)s1 * H + g * 4);
        acc.x += v0.x + v1.x; acc.y += v0.y + v1.y;
        acc.z += v0.z + v1.z; acc.w += v0.w + v1.w;
    }
    if (e < end) {
        int s = g_csr[e];
        float4 v = *reinterpret_cast<const float4*>(g_h1 + (size_t)s * H + g * 4);
        acc.x += v.x; acc.y += v.y; acc.z += v.z; acc.w += v.w;
    }
    acc.x += __shfl_xor_sync(0xffffffff, acc.x, 16);
    acc.y += __shfl_xor_sync(0xffffffff, acc.y, 16);
    acc.z += __shfl_xor_sync(0xffffffff, acc.z, 16);
    acc.w += __shfl_xor_sync(0xffffffff, acc.w, 16);
    if (lane < 16) {
        float inv = 1.f / fmaxf((float)deg, 1.f);
        acc.x *= inv; acc.y *= inv; acc.z *= inv; acc.w *= inv;
        *reinterpret_cast<float4*>(g_agg2 + (size_t)n * H + g * 4) = acc;
    }
}

// ---------------- layer-2 node update + pooling: k-chunked acc[64] ----------
// inputs streamed once; acc[] statically indexed (fully unrolled inner j loop)
__global__ void __launch_bounds__(128) k_node2(const void* __restrict__ batch,
                                               const float* __restrict__ Wl,
                                               const float* __restrict__ b,
                                               const float* __restrict__ Wr) {
    __shared__ __align__(16) float sWl[H * H];
    __shared__ __align__(16) float sWr[H * H];
    __shared__ float sb[H];
    for (int i = threadIdx.x; i < H * H; i += blockDim.x) { sWl[i] = Wl[i]; sWr[i] = Wr[i]; }
    for (int i = threadIdx.x; i < H; i += blockDim.x) sb[i] = b[i];
    __syncthreads();

    int n = blockIdx.x * blockDim.x + threadIdx.x;
    if (n >= N_NODES) return;

    float acc[H];
#pragma unroll
    for (int j = 0; j < H; j++) acc[j] = sb[j];

    const float4* ag = reinterpret_cast<const float4*>(g_agg2 + (size_t)n * H);
    const float4* hr = reinterpret_cast<const float4*>(g_h1 + (size_t)n * H);

#pragma unroll 1
    for (int kc = 0; kc < H / 4; kc++) {
        float4 a = ag[kc];
        float4 hb = hr[kc];
#pragma unroll
        for (int j = 0; j < H; j++) {
            float4 wl = *reinterpret_cast<const float4*>(&sWl[j * H + kc * 4]);
            float4 wr = *reinterpret_cast<const float4*>(&sWr[j * H + kc * 4]);
            acc[j] += a.x * wl.x + a.y * wl.y + a.z * wl.z + a.w * wl.w
                    + hb.x * wr.x + hb.y * wr.y + hb.z * wr.z + hb.w * wr.w;
        }
    }

    int bg = load_idx(batch, n);
    float* poolrow = g_pool + (size_t)bg * H;
#pragma unroll
    for (int j = 0; j < H; j += 4) {
        float4 o;
        o.x = fmaxf(acc[j + 0], 0.f); o.y = fmaxf(acc[j + 1], 0.f);
        o.z = fmaxf(acc[j + 2], 0.f); o.w = fmaxf(acc[j + 3], 0.f);
        atomicAdd(reinterpret_cast<float4*>(poolrow + j), o);
    }
    atomicAdd(&g_cnt[bg], 1.0f);
}

// ---------------- final linear ----------------------------------------------
__global__ void k_final(const float* __restrict__ Wlin,
                        const float* __restrict__ blin,
                        float* __restrict__ out) {
    int g = blockIdx.x * blockDim.x + threadIdx.x;
    if (g >= N_GRAPHS) return;
    float invc = 1.0f / fmaxf(g_cnt[g], 1.0f);
    float a0 = blin[0], a1 = blin[1];
#pragma unroll
    for (int j = 0; j < H; j++) {
        float p = g_pool[(size_t)g * H + j] * invc;
        a0 += p * Wlin[j];
        a1 += p * Wlin[H + j];
    }
    out[g * 2 + 0] = a0;
    out[g * 2 + 1] = a1;
}

// ---------------------------------------------------------------------------
extern "C" void kernel_launch(void* const* d_in, const int* in_sizes, int n_in,
                              void* d_out, int out_size) {
    const float* x     = (const float*)d_in[0];
    const void*  ei    = d_in[1];
    const void*  batch = d_in[2];
    const float* W1_l  = (const float*)d_in[3];
    const float* b1    = (const float*)d_in[4];
    const float* W1_r  = (const float*)d_in[5];
    const float* W2_l  = (const float*)d_in[6];
    const float* b2    = (const float*)d_in[7];
    const float* W2_r  = (const float*)d_in[8];
    const float* W_lin = (const float*)d_in[9];
    const float* b_lin = (const float*)d_in[10];
    float* out = (float*)d_out;

    int E = in_sizes[1] / 2;
    int eb = (E + 255) / 256;
    int nb8 = (N_NODES + 7) / 8;

    k_zero<<<256, 256>>>(ei, in_sizes[1]);
    k_hist<<<eb, 256>>>(ei, E);
    k_scan1<<<NBLK, 256>>>();
    k_scan2<<<1, 1024>>>();
    k_scan3<<<NBLK, 256>>>();
    k_scatter<<<eb, 256>>>(ei, E);
    k_gather1<<<nb8, 256>>>(x);
    k_node1<<<(N_NODES + 255) / 256, 256>>>(x, W1_l, b1, W1_r);
    k_gather2<<<nb8, 256>>>();
    k_node2<<<(N_NODES + 127) / 128, 128>>>(batch, W2_l, b2, W2_r);
    k_final<<<(N_GRAPHS + 127) / 128, 128>>>(W_lin, b_lin, out);
}